// round 3
// baseline (speedup 1.0000x reference)
#include <cuda_runtime.h>
#include <cuda_bf16.h>
#include <math.h>

// Problem constants
#define BATCH 4
#define SEQ   2048
#define EMB   1024     // H * Dk
#define HEADS 16
#define KDIM  64
#define PROJK 256
#define MROWS (BATCH * SEQ)   // 8192

// ---------------- scratch (allocation-free) ----------------
// g_k doubles as ctx: k is fully consumed by proj_kernel before
// attn_kernel writes ctx (same stream => ordered).
__device__ float g_q  [MROWS * EMB];
__device__ float g_k  [MROWS * EMB];
__device__ float g_v  [MROWS * EMB];
__device__ float g_kp [BATCH * PROJK * EMB];
__device__ float g_vp [BATCH * PROJK * EMB];

// ================================================================
// SGEMM: C[M,N] = (A[M,K] @ B[K,N] + bias[N]) * alpha
// BM=128, BN=128, BK=8, TM=8, TN=8, 256 threads
// Register-prefetch software pipeline over k-tiles.
// grid = (N/128, M/128)
// ================================================================
__global__ __launch_bounds__(256)
void sgemm_bias_kernel(const float* __restrict__ A,
                       const float* __restrict__ B,
                       const float* __restrict__ bias,
                       float* __restrict__ C,
                       int M, int N, int K, float alpha)
{
    __shared__ float As[8][128];   // As[k][m]
    __shared__ float Bs[8][128];   // Bs[k][n]

    const int tid = threadIdx.x;
    const int tx  = tid % 16;      // n-group
    const int ty  = tid / 16;      // m-group

    const float* Ab = A + (size_t)blockIdx.y * 128 * K;
    const float* Bb = B + blockIdx.x * 128;

    // load mapping
    const int aRow  = tid >> 1;          // 0..127
    const int aCol4 = (tid & 1) * 4;     // 0 or 4
    const int bRow  = tid >> 5;          // 0..7
    const int bCol4 = (tid & 31) * 4;    // 0..124

    float acc[8][8];
#pragma unroll
    for (int i = 0; i < 8; i++)
#pragma unroll
        for (int j = 0; j < 8; j++) acc[i][j] = 0.f;

    // prologue: load first tile
    float4 av = *(const float4*)(Ab + (size_t)aRow * K + aCol4);
    float4 bv = *(const float4*)(Bb + (size_t)bRow * N + bCol4);

    for (int k0 = 0; k0 < K; k0 += 8) {
        // store current tile to smem
        As[aCol4 + 0][aRow] = av.x;
        As[aCol4 + 1][aRow] = av.y;
        As[aCol4 + 2][aRow] = av.z;
        As[aCol4 + 3][aRow] = av.w;
        *(float4*)(&Bs[bRow][bCol4]) = bv;
        __syncthreads();

        // prefetch next tile into registers (overlaps with FMA burst)
        if (k0 + 8 < K) {
            av = *(const float4*)(Ab + (size_t)aRow * K + (k0 + 8) + aCol4);
            bv = *(const float4*)(Bb + (size_t)(k0 + 8 + bRow) * N + bCol4);
        }

#pragma unroll
        for (int kk = 0; kk < 8; kk++) {
            float a[8], b[8];
#pragma unroll
            for (int i = 0; i < 8; i++) a[i] = As[kk][ty * 8 + i];
#pragma unroll
            for (int j = 0; j < 8; j++) b[j] = Bs[kk][tx * 8 + j];
#pragma unroll
            for (int i = 0; i < 8; i++)
#pragma unroll
                for (int j = 0; j < 8; j++)
                    acc[i][j] = fmaf(a[i], b[j], acc[i][j]);
        }
        __syncthreads();
    }

    // epilogue
#pragma unroll
    for (int i = 0; i < 8; i++) {
        int row = blockIdx.y * 128 + ty * 8 + i;
#pragma unroll
        for (int j4 = 0; j4 < 8; j4 += 4) {
            int col = blockIdx.x * 128 + tx * 8 + j4;
            float4 o;
            o.x = (acc[i][j4 + 0] + bias[col + 0]) * alpha;
            o.y = (acc[i][j4 + 1] + bias[col + 1]) * alpha;
            o.z = (acc[i][j4 + 2] + bias[col + 2]) * alpha;
            o.w = (acc[i][j4 + 3] + bias[col + 3]) * alpha;
            *(float4*)(&C[(size_t)row * N + col]) = o;
        }
    }
}

// ================================================================
// Sequence projection (batched, A-transposed GEMM):
// C[b][m][n] = sum_s E[s*PROJK + m] * X[b][s][n] + bias[m]
// m in [0,PROJK), n in [0,EMB), s in [0,SEQ)
// BM=64, BN=64, BK=16, TM=4, TN=4, 256 threads
// grid = (EMB/64, PROJK/64, BATCH)
// ================================================================
__global__ __launch_bounds__(256)
void proj_kernel(const float* __restrict__ E,
                 const float* __restrict__ X,
                 const float* __restrict__ bias,
                 float* __restrict__ C)
{
    __shared__ float As[16][64];   // As[k][m]
    __shared__ float Bs[16][64];   // Bs[k][n]

    const int tid = threadIdx.x;
    const int tx  = tid % 16;
    const int ty  = tid / 16;
    const int b   = blockIdx.z;
    const int m0  = blockIdx.y * 64;
    const int n0  = blockIdx.x * 64;

    const float* Xb = X + (size_t)b * SEQ * EMB;

    const int lk  = tid >> 4;          // 0..15
    const int l4  = (tid & 15) * 4;    // 0..60

    float acc[4][4];
#pragma unroll
    for (int i = 0; i < 4; i++)
#pragma unroll
        for (int j = 0; j < 4; j++) acc[i][j] = 0.f;

    float4 av = *(const float4*)(E  + (size_t)lk * PROJK + m0 + l4);
    float4 bv = *(const float4*)(Xb + (size_t)lk * EMB   + n0 + l4);

    for (int k0 = 0; k0 < SEQ; k0 += 16) {
        *(float4*)(&As[lk][l4]) = av;
        *(float4*)(&Bs[lk][l4]) = bv;
        __syncthreads();

        if (k0 + 16 < SEQ) {
            av = *(const float4*)(E  + (size_t)(k0 + 16 + lk) * PROJK + m0 + l4);
            bv = *(const float4*)(Xb + (size_t)(k0 + 16 + lk) * EMB   + n0 + l4);
        }

#pragma unroll
        for (int kk = 0; kk < 16; kk++) {
            float a[4], b2[4];
#pragma unroll
            for (int i = 0; i < 4; i++) a[i]  = As[kk][ty * 4 + i];
#pragma unroll
            for (int j = 0; j < 4; j++) b2[j] = Bs[kk][tx * 4 + j];
#pragma unroll
            for (int i = 0; i < 4; i++)
#pragma unroll
                for (int j = 0; j < 4; j++)
                    acc[i][j] = fmaf(a[i], b2[j], acc[i][j]);
        }
        __syncthreads();
    }

#pragma unroll
    for (int i = 0; i < 4; i++) {
        int m = m0 + ty * 4 + i;
        float bm = bias[m];
        float4 o;
        o.x = acc[i][0] + bm;
        o.y = acc[i][1] + bm;
        o.z = acc[i][2] + bm;
        o.w = acc[i][3] + bm;
        *(float4*)(&C[((size_t)b * PROJK + m) * EMB + n0 + tx * 4]) = o;
    }
}

// ================================================================
// Fused attention:
//   scores = q_h[64rows,64] @ khT[64,256]; softmax over 256;
//   ctx    = attn @ vh[256,64]
// Block: 256 threads = 8 warps, each warp handles 8 query rows.
// grid = (SEQ/64, HEADS, BATCH), dynamic smem ~176KB.
// q already scaled by Dk^-0.5 in its GEMM epilogue.
// ================================================================
#define KHT_STRIDE 257
__global__ __launch_bounds__(256)
void attn_kernel(const float* __restrict__ q,
                 const float* __restrict__ kproj,
                 const float* __restrict__ vproj,
                 float* __restrict__ ctx)
{
    extern __shared__ float sm[];
    float* khT = sm;                           // [64][257]   khT[d][kp]
    float* vh  = khT + 64 * KHT_STRIDE;        // [256][64]   vh[kp][d]
    float* qs  = vh + 256 * 64;                // [64][64]
    float* ps  = qs + 64 * 64;                 // [8 warps][4][256]

    const int b    = blockIdx.z;
    const int h    = blockIdx.y;
    const int s0   = blockIdx.x * 64;
    const int tid  = threadIdx.x;
    const int w    = tid >> 5;
    const int lane = tid & 31;

    const float* kpB = kproj + ((size_t)b * PROJK) * EMB + h * KDIM;
    const float* vpB = vproj + ((size_t)b * PROJK) * EMB + h * KDIM;
    for (int i = tid; i < PROJK * KDIM; i += 256) {
        int kp = i >> 6, d = i & 63;
        khT[d * KHT_STRIDE + kp] = kpB[(size_t)kp * EMB + d];
        vh[i]                    = vpB[(size_t)kp * EMB + d];
    }
    const float* qB = q + ((size_t)(b * SEQ + s0)) * EMB + h * KDIM;
    for (int i = tid; i < 64 * 64; i += 256) {
        int r = i >> 6, d = i & 63;
        qs[i] = qB[(size_t)r * EMB + d];
    }
    __syncthreads();

    float* myp = ps + w * 4 * 256;

    for (int g = 0; g < 2; g++) {
        const int rbase = w * 8 + g * 4;

        // ---- scores: s[r][j] for kp = lane + 32*j ----
        float s[4][8];
#pragma unroll
        for (int r = 0; r < 4; r++)
#pragma unroll
            for (int j = 0; j < 8; j++) s[r][j] = 0.f;

#pragma unroll 4
        for (int d = 0; d < 64; d++) {
            float kv[8];
#pragma unroll
            for (int j = 0; j < 8; j++)
                kv[j] = khT[d * KHT_STRIDE + lane + 32 * j];
#pragma unroll
            for (int r = 0; r < 4; r++) {
                float qv = qs[(rbase + r) * 64 + d];
#pragma unroll
                for (int j = 0; j < 8; j++)
                    s[r][j] = fmaf(qv, kv[j], s[r][j]);
            }
        }

        // ---- softmax per row ----
        float inv[4];
#pragma unroll
        for (int r = 0; r < 4; r++) {
            float m = s[r][0];
#pragma unroll
            for (int j = 1; j < 8; j++) m = fmaxf(m, s[r][j]);
#pragma unroll
            for (int o = 16; o > 0; o >>= 1)
                m = fmaxf(m, __shfl_xor_sync(0xFFFFFFFFu, m, o));
            float sum = 0.f;
#pragma unroll
            for (int j = 0; j < 8; j++) {
                s[r][j] = __expf(s[r][j] - m);
                sum += s[r][j];
            }
#pragma unroll
            for (int o = 16; o > 0; o >>= 1)
                sum += __shfl_xor_sync(0xFFFFFFFFu, sum, o);
            inv[r] = 1.f / sum;
#pragma unroll
            for (int j = 0; j < 8; j++)
                myp[r * 256 + lane + 32 * j] = s[r][j];
        }
        __syncwarp();

        // ---- ctx: acc[r][d-half] = sum_kp p * vh ----
        float acc[4][2];
#pragma unroll
        for (int r = 0; r < 4; r++) { acc[r][0] = 0.f; acc[r][1] = 0.f; }

#pragma unroll 4
        for (int kp = 0; kp < 256; kp++) {
            float v0 = vh[kp * 64 + lane];
            float v1 = vh[kp * 64 + lane + 32];
#pragma unroll
            for (int r = 0; r < 4; r++) {
                float p = myp[r * 256 + kp];
                acc[r][0] = fmaf(p, v0, acc[r][0]);
                acc[r][1] = fmaf(p, v1, acc[r][1]);
            }
        }

#pragma unroll
        for (int r = 0; r < 4; r++) {
            size_t row = (size_t)(b * SEQ + s0 + rbase + r);
            ctx[row * EMB + h * KDIM + lane]      = acc[r][0] * inv[r];
            ctx[row * EMB + h * KDIM + lane + 32] = acc[r][1] * inv[r];
        }
        __syncwarp();   // myp reused next g
    }
}

// ================================================================
// Launch
// ================================================================
extern "C" void kernel_launch(void* const* d_in, const int* in_sizes, int n_in,
                              void* d_out, int out_size)
{
    const float* query = (const float*)d_in[0];
    const float* value = (const float*)d_in[1];
    const float* Wq    = (const float*)d_in[2];
    const float* bq    = (const float*)d_in[3];
    const float* Wk    = (const float*)d_in[4];
    const float* bk    = (const float*)d_in[5];
    const float* Wv    = (const float*)d_in[6];
    const float* bv    = (const float*)d_in[7];
    const float* Wo    = (const float*)d_in[8];
    const float* bo    = (const float*)d_in[9];
    const float* E     = (const float*)d_in[10];
    const float* Eb    = (const float*)d_in[11];
    const float* F     = (const float*)d_in[12];
    const float* Fb    = (const float*)d_in[13];
    float* out = (float*)d_out;

    float *gq, *gk, *gv, *gkp, *gvp;
    cudaGetSymbolAddress((void**)&gq,   g_q);
    cudaGetSymbolAddress((void**)&gk,   g_k);
    cudaGetSymbolAddress((void**)&gv,   g_v);
    cudaGetSymbolAddress((void**)&gkp,  g_kp);
    cudaGetSymbolAddress((void**)&gvp,  g_vp);
    float* gctx = gk;   // alias: k dead after proj_kernel, same stream

    const float scale = 1.0f / 8.0f;   // 64^-0.5

    dim3 gemm_grid(EMB / 128, MROWS / 128);   // (8, 64)
    // QKV projections (Dk^-0.5 folded into q)
    sgemm_bias_kernel<<<gemm_grid, 256>>>(query, Wq, bq, gq, MROWS, EMB, EMB, scale);
    sgemm_bias_kernel<<<gemm_grid, 256>>>(value, Wk, bk, gk, MROWS, EMB, EMB, 1.0f);
    sgemm_bias_kernel<<<gemm_grid, 256>>>(value, Wv, bv, gv, MROWS, EMB, EMB, 1.0f);

    // Linformer sequence projections
    dim3 proj_grid(EMB / 64, PROJK / 64, BATCH);  // (16, 4, 4)
    proj_kernel<<<proj_grid, 256>>>(E, gk, Eb, gkp);
    proj_kernel<<<proj_grid, 256>>>(F, gv, Fb, gvp);

    // Fused attention
    size_t attn_smem = (size_t)(64 * KHT_STRIDE + 256 * 64 + 64 * 64 + 8 * 4 * 256) * sizeof(float);
    cudaFuncSetAttribute(attn_kernel, cudaFuncAttributeMaxDynamicSharedMemorySize, (int)attn_smem);
    dim3 attn_grid(SEQ / 64, HEADS, BATCH);       // (32, 16, 4)
    attn_kernel<<<attn_grid, 256, attn_smem>>>(gq, gkp, gvp, gctx);

    // Output projection
    sgemm_bias_kernel<<<gemm_grid, 256>>>(gctx, Wo, bo, out, MROWS, EMB, EMB, 1.0f);
}